// round 7
// baseline (speedup 1.0000x reference)
#include <cuda_runtime.h>
#include <cstdint>

#define EPSF 1e-7f
typedef unsigned long long u64t;
typedef unsigned int u32t;

constexpr int Bb = 32;
constexpr int Ii = 32;
constexpr int Oo = 64;
constexpr int Pp = 16;
constexpr int Nn = 2048;
constexpr int CHUNKS = 16;   // 4 spatial per block
constexpr int ROWS = 128;    // 4 spatial * 32 i
constexpr int WS = 20;       // padded stride for mean/inv (conflict-free LDS128)
constexpr int AS = 17;       // padded stride for smem accumulators (conflict-free ATOMS)

// Global scratch (device globals; no cudaMalloc allowed)
__device__ float g_S0[Bb][Oo];
__device__ float g_S1[Bb][Oo][Pp];
__device__ float g_S2[Bb][Oo][Pp];
__device__ float g_mean[Bb][Oo][Pp];
__device__ float g_inv2var[Bb][Oo][Pp];
__device__ float g_ll[Bb][Oo];              // log(act+eps) - lsum (fused)
__device__ ulonglong2 g_wT2[Ii * 4 * Oo];   // W: [ic][k][o] -> {pair(c0,c1), pair(c2,c3)}

// ---- f32x2 packed helpers ----
__device__ __forceinline__ u64t pk2(float lo, float hi) {
    u64t r; asm("mov.b64 %0,{%1,%2};" : "=l"(r) : "f"(lo), "f"(hi)); return r;
}
__device__ __forceinline__ void up2(u64t a, float& lo, float& hi) {
    asm("mov.b64 {%0,%1},%2;" : "=f"(lo), "=f"(hi) : "l"(a));
}
__device__ __forceinline__ u64t fma2(u64t a, u64t b, u64t c) {
    u64t d; asm("fma.rn.f32x2 %0,%1,%2,%3;" : "=l"(d) : "l"(a), "l"(b), "l"(c)); return d;
}
__device__ __forceinline__ u64t add2(u64t a, u64t b) {
    u64t d; asm("add.rn.f32x2 %0,%1,%2;" : "=l"(d) : "l"(a), "l"(b)); return d;
}
__device__ __forceinline__ u64t mul2(u64t a, u64t b) {
    u64t d; asm("mul.rn.f32x2 %0,%1,%2;" : "=l"(d) : "l"(a), "l"(b)); return d;
}
// ---- warp reductions (redux.sync.f32 not in sm_103 ISA) ----
__device__ __forceinline__ float warp_max(float v) {
    #pragma unroll
    for (int off = 16; off >= 1; off >>= 1)
        v = fmaxf(v, __shfl_xor_sync(0xffffffffu, v, off));
    return v;
}
__device__ __forceinline__ float warp_add(float v) {
    #pragma unroll
    for (int off = 16; off >= 1; off >>= 1)
        v += __shfl_xor_sync(0xffffffffu, v, off);
    return v;
}
// ---- cp.async 16B (L1-bypass) ----
__device__ __forceinline__ void cpasync16(u32t saddr, const void* g) {
    asm volatile("cp.async.cg.shared.global [%0], [%1], 16;" :: "r"(saddr), "l"(g));
}
__device__ __forceinline__ void cp_commit() {
    asm volatile("cp.async.commit_group;");
}
__device__ __forceinline__ void cp_wait1() {
    asm volatile("cp.async.wait_group 1;");
}

// One-time prep: transpose W to o-contiguous dual-pairs, zero accumulators.
__global__ void prep_kernel(const float* __restrict__ w) {
    int idx = blockIdx.x * 256 + threadIdx.x;   // grid covers 32768
    if (idx < Ii * 4 * Oo) {
        int o = idx & 63, k = (idx >> 6) & 3, ic = idx >> 8;
        const float4 s = *(const float4*)(w + ((ic * Oo + o) * 16 + k * 4));
        ulonglong2 d;
        d.x = ((u64t)__float_as_uint(s.y) << 32) | __float_as_uint(s.x);
        d.y = ((u64t)__float_as_uint(s.w) << 32) | __float_as_uint(s.z);
        g_wT2[idx] = d;
    }
    float* s0 = &g_S0[0][0];
    float* s1 = &g_S1[0][0][0];
    float* s2 = &g_S2[0][0][0];
    if (idx < Bb * Oo) s0[idx] = 0.0f;
    if (idx < Bb * Oo * Pp) { s1[idx] = 0.0f; s2[idx] = 0.0f; }
}

// smem: core 7040 floats (27.5KB) + W ring 3*256 ulonglong2 (12KB) = 39.7KB
template<bool FIRST>
__global__ __launch_bounds__(128, 4)
void stats_kernel(const float* __restrict__ gpose,
                  const float* __restrict__ gact)
{
    __shared__ float sm[7040];
    __shared__ __align__(16) ulonglong2 wring[3 * 256];
    float* sMean = sm;             // negated mean, stride WS
    float* sInv  = sm + 1280;      // 1/(2 var), stride WS
    float* sLL   = sm + 2560;
    float* sPose = sm + 2624;
    float* sAct  = sm + 4672;
    float* sAcc0 = sm + 4800;
    float* sAcc1 = sm + 4864;      // stride AS per o
    float* sAcc2 = sm + 5952;

    const int tid   = threadIdx.x;
    const int b     = blockIdx.y;
    const int chunk = blockIdx.x;

    const u32t wring_sa = (u32t)__cvta_generic_to_shared(wring);

    // ---- prologue: prefetch W for ic=0,1 into ring stages 0,1 ----
    #pragma unroll
    for (int pre = 0; pre < 2; pre++) {
        const char* gsrc = (const char*)(g_wT2 + pre * 256);
        cpasync16(wring_sa + pre * 4096 + tid * 16,         gsrc + tid * 16);
        cpasync16(wring_sa + pre * 4096 + (tid + 128) * 16, gsrc + (tid + 128) * 16);
        cp_commit();
    }

    // ---- stage pose + act ----
    const float4* gp4 = (const float4*)(gpose + ((size_t)(b * Nn + chunk * ROWS)) * 16);
    #pragma unroll
    for (int i = 0; i < 4; i++)
        ((float4*)sPose)[tid + 128 * i] = gp4[tid + 128 * i];
    sAct[tid] = gact[b * Nn + chunk * ROWS + tid];

    if (!FIRST) {
        for (int idx = tid; idx < Oo * Pp; idx += 128) {
            int o = idx >> 4, p = idx & 15;
            sMean[o * WS + p] = -g_mean[b][o][p];
            sInv[o * WS + p]  = g_inv2var[b][o][p];
        }
        if (tid < Oo) sLL[tid] = g_ll[b][tid];
    }
    for (int idx = tid; idx < 64 + 2 * 1088; idx += 128) sAcc0[idx] = 0.0f;
    __syncthreads();

    const int wid  = tid >> 5;
    const int lane = tid & 31;
    const int sp   = chunk * 4 + wid;              // global spatial [0,64)
    const float chv = ((sp >> 3) + 0.5f) * 0.125f;
    const float cwv = ((sp & 7) + 0.5f) * 0.125f;

    float ll0 = 0.0f, ll1 = 0.0f;
    if (!FIRST) { ll0 = sLL[lane]; ll1 = sLL[lane + 32]; }

    u64t A1[2][8], A2[2][8];
    float A0[2] = {0.0f, 0.0f};
    #pragma unroll
    for (int j = 0; j < 2; j++)
        #pragma unroll
        for (int r2 = 0; r2 < 8; r2++) { A1[j][r2] = 0ull; A2[j][r2] = 0ull; }

    int stage = 0;       // ic % 3
    int nstage = 2;      // (ic+2) % 3
    for (int ic = 0; ic < Ii; ic++) {
        // wait for W[ic] (leave W[ic+1] in flight), sync so all warps see it
        cp_wait1();
        __syncthreads();
        // prefetch W[ic+2] into stage (ic+2)%3 (safe: all warps done with ic-1)
        if (ic + 2 < Ii) {
            const char* gsrc = (const char*)(g_wT2 + (ic + 2) * 256);
            cpasync16(wring_sa + nstage * 4096 + tid * 16,         gsrc + tid * 16);
            cpasync16(wring_sa + nstage * 4096 + (tid + 128) * 16, gsrc + (tid + 128) * 16);
        }
        cp_commit();   // (possibly empty group; keeps wait arithmetic uniform)

        const ulonglong2* wb = wring + stage * 256;
        const int r = wid * 32 + ic;

        // pose row -> 16 floats (broadcast LDS128)
        float pr[16];
        {
            const float4* pp = (const float4*)&sPose[r * 16];
            #pragma unroll
            for (int q = 0; q < 4; q++) {
                float4 t = pp[q];
                pr[q*4+0] = t.x; pr[q*4+1] = t.y; pr[q*4+2] = t.z; pr[q*4+3] = t.w;
            }
        }
        const float a_n = sAct[r];

        u64t v2[2][8];
        float zz[2] = {0.0f, 0.0f};

        #pragma unroll
        for (int j2 = 0; j2 < 2; j2++) {
            const int o = lane + 32 * j2;
            u64t* v = v2[j2];
            v[0] = pk2(chv, cwv);
            #pragma unroll
            for (int r2 = 1; r2 < 8; r2++) v[r2] = 0ull;

            #pragma unroll
            for (int k = 0; k < 4; k++) {
                ulonglong2 wk = wb[k * 64 + o];    // LDS.128, conflict-free
                #pragma unroll
                for (int a = 0; a < 4; a++) {
                    u64t pa = pk2(pr[a*4+k], pr[a*4+k]);
                    v[a*2+0] = fma2(pa, wk.x, v[a*2+0]);
                    v[a*2+1] = fma2(pa, wk.y, v[a*2+1]);
                }
            }

            if (!FIRST) {
                u64t acc = 0ull;
                const ulonglong2* mr = (const ulonglong2*)&sMean[o * WS];
                const ulonglong2* ir = (const ulonglong2*)&sInv[o * WS];
                #pragma unroll
                for (int q = 0; q < 4; q++) {
                    ulonglong2 m  = mr[q];
                    ulonglong2 iv = ir[q];
                    u64t d0 = add2(v[q*2+0], m.x);   // mean pre-negated
                    acc = fma2(mul2(d0, d0), iv.x, acc);
                    u64t d1 = add2(v[q*2+1], m.y);
                    acc = fma2(mul2(d1, d1), iv.y, acc);
                }
                float al, ah; up2(acc, al, ah);
                zz[j2] = (j2 ? ll1 : ll0) - (al + ah);
            }
        }

        float rrp[2];
        if (!FIRST) {
            float m = warp_max(fmaxf(zz[0], zz[1]));
            float e0 = __expf(zz[0] - m);
            float e1 = __expf(zz[1] - m);
            float s = warp_add(e0 + e1);
            float scale = __fdividef(a_n, s);
            rrp[0] = e0 * scale;
            rrp[1] = e1 * scale;
        } else {
            rrp[0] = rrp[1] = a_n * (1.0f / 64.0f);
        }

        #pragma unroll
        for (int j2 = 0; j2 < 2; j2++) {
            A0[j2] += rrp[j2];
            u64t rp = pk2(rrp[j2], rrp[j2]);
            #pragma unroll
            for (int r2 = 0; r2 < 8; r2++) {
                u64t t = mul2(rp, v2[j2][r2]);
                A1[j2][r2] = add2(A1[j2][r2], t);
                A2[j2][r2] = fma2(t, v2[j2][r2], A2[j2][r2]);
            }
        }

        stage = (stage == 2) ? 0 : stage + 1;
        nstage = (nstage == 2) ? 0 : nstage + 1;
    }

    // ---- cross-warp reduction (conflict-free smem atomics, stride AS) ----
    #pragma unroll
    for (int j2 = 0; j2 < 2; j2++) {
        const int o = lane + 32 * j2;
        atomicAdd(&sAcc0[o], A0[j2]);
        #pragma unroll
        for (int r2 = 0; r2 < 8; r2++) {
            float l1, h1, l2h, h2h;
            up2(A1[j2][r2], l1, h1);
            up2(A2[j2][r2], l2h, h2h);
            atomicAdd(&sAcc1[o * AS + 2*r2],     l1);
            atomicAdd(&sAcc1[o * AS + 2*r2 + 1], h1);
            atomicAdd(&sAcc2[o * AS + 2*r2],     l2h);
            atomicAdd(&sAcc2[o * AS + 2*r2 + 1], h2h);
        }
    }
    __syncthreads();

    // ---- flush partials to global accumulators ----
    float* gs0 = &g_S0[b][0];
    float* gs1 = &g_S1[b][0][0];
    float* gs2 = &g_S2[b][0][0];
    for (int idx = tid; idx < Oo; idx += 128) atomicAdd(&gs0[idx], sAcc0[idx]);
    for (int idx = tid; idx < Oo * Pp; idx += 128) {
        int o = idx >> 4, p = idx & 15;
        atomicAdd(&gs1[idx], sAcc1[o * AS + p]);
        atomicAdd(&gs2[idx], sAcc2[o * AS + p]);
    }
}

__global__ __launch_bounds__(64)
void finalize_kernel(int it,
                     const float* __restrict__ beta_v,
                     const float* __restrict__ beta_a,
                     float* __restrict__ out)
{
    __shared__ float sCost[Oo];
    const int b = blockIdx.x;
    const int o = threadIdx.x;

    const float rps = g_S0[b][o];
    const float inv_rps = 1.0f / rps;
    float mean[16], inv2v[16];
    float lsum = 0.0f;
    #pragma unroll
    for (int p = 0; p < 16; p++) {
        float m = g_S1[b][o][p] * inv_rps;
        float var = g_S2[b][o][p] * inv_rps - m * m;
        var = fmaxf(var, 0.0f);
        float sd = sqrtf(var);
        mean[p] = m;
        inv2v[p] = 0.5f / var;
        lsum += __logf(sd + EPSF);
    }
    const float cost = (16.0f * beta_v[o] + lsum) * rps;
    sCost[o] = cost;
    __syncthreads();

    float cm = 0.0f;
    for (int q = 0; q < Oo; q++) cm += sCost[q];
    cm *= (1.0f / 64.0f);
    float cv = 0.0f;
    for (int q = 0; q < Oo; q++) { float d = sCost[q] - cm; cv += d * d; }
    const float cstd = sqrtf(cv * (1.0f / 64.0f));

    const float inv_temp = 1.0f + (float)it;
    const float x = inv_temp * (beta_a[o] + (cm - cost) / (cstd + EPSF));
    const float oact = 1.0f / (1.0f + __expf(-x));

    if (it < 2) {
        g_ll[b][o] = __logf(oact + EPSF) - lsum;
        #pragma unroll
        for (int p = 0; p < 16; p++) {
            g_mean[b][o][p] = mean[p];
            g_inv2var[b][o][p] = inv2v[p];
        }
        g_S0[b][o] = 0.0f;
        #pragma unroll
        for (int p = 0; p < 16; p++) { g_S1[b][o][p] = 0.0f; g_S2[b][o][p] = 0.0f; }
    } else {
        #pragma unroll
        for (int p = 0; p < 16; p++) out[(b * Oo + o) * 16 + p] = mean[p];
        out[Bb * Oo * Pp + b * Oo + o] = oact;
    }
}

extern "C" void kernel_launch(void* const* d_in, const int* in_sizes, int n_in,
                              void* d_out, int out_size)
{
    const float* pose = (const float*)d_in[0];
    const float* act  = (const float*)d_in[1];
    const float* w    = (const float*)d_in[2];
    const float* bv   = (const float*)d_in[3];
    const float* ba   = (const float*)d_in[4];
    float* out = (float*)d_out;

    prep_kernel<<<128, 256>>>(w);
    stats_kernel<true><<<dim3(CHUNKS, Bb), 128>>>(pose, act);
    finalize_kernel<<<Bb, 64>>>(0, bv, ba, out);
    stats_kernel<false><<<dim3(CHUNKS, Bb), 128>>>(pose, act);
    finalize_kernel<<<Bb, 64>>>(1, bv, ba, out);
    stats_kernel<false><<<dim3(CHUNKS, Bb), 128>>>(pose, act);
    finalize_kernel<<<Bb, 64>>>(2, bv, ba, out);
}

// round 8
// speedup vs baseline: 1.3721x; 1.3721x over previous
#include <cuda_runtime.h>
#include <cstdint>

#define EPSF 1e-7f
typedef unsigned long long u64t;

constexpr int Bb = 32;
constexpr int Ii = 32;
constexpr int Oo = 64;
constexpr int Pp = 16;
constexpr int Nn = 2048;
constexpr int CHUNKS = 16;   // 4 spatial per block
constexpr int ROWS = 128;    // 4 spatial * 32 i
constexpr int WS = 20;       // padded stride for mean/inv (conflict-free LDS128)
constexpr int AS = 17;       // padded stride for smem accumulators (conflict-free ATOMS)

// Global scratch (device globals; no cudaMalloc allowed)
__device__ float g_S0[Bb][Oo];
__device__ float g_S1[Bb][Oo][Pp];
__device__ float g_S2[Bb][Oo][Pp];
__device__ float g_mean[Bb][Oo][Pp];
__device__ float g_inv2var[Bb][Oo][Pp];
__device__ float g_ll[Bb][Oo];              // log(act+eps) - lsum (fused)
__device__ ulonglong2 g_wT2[Ii * 4 * Oo];   // W: [ic][k][o] -> {pair(c0,c1), pair(c2,c3)}

// ---- f32x2 packed helpers ----
__device__ __forceinline__ u64t pk2(float lo, float hi) {
    u64t r; asm("mov.b64 %0,{%1,%2};" : "=l"(r) : "f"(lo), "f"(hi)); return r;
}
__device__ __forceinline__ void up2(u64t a, float& lo, float& hi) {
    asm("mov.b64 {%0,%1},%2;" : "=f"(lo), "=f"(hi) : "l"(a));
}
__device__ __forceinline__ u64t fma2(u64t a, u64t b, u64t c) {
    u64t d; asm("fma.rn.f32x2 %0,%1,%2,%3;" : "=l"(d) : "l"(a), "l"(b), "l"(c)); return d;
}
__device__ __forceinline__ u64t add2(u64t a, u64t b) {
    u64t d; asm("add.rn.f32x2 %0,%1,%2;" : "=l"(d) : "l"(a), "l"(b)); return d;
}
__device__ __forceinline__ u64t mul2(u64t a, u64t b) {
    u64t d; asm("mul.rn.f32x2 %0,%1,%2;" : "=l"(d) : "l"(a), "l"(b)); return d;
}
// ---- warp reductions (redux.sync.f32 not in sm_103 ISA) ----
__device__ __forceinline__ float warp_max(float v) {
    #pragma unroll
    for (int off = 16; off >= 1; off >>= 1)
        v = fmaxf(v, __shfl_xor_sync(0xffffffffu, v, off));
    return v;
}
__device__ __forceinline__ float warp_add(float v) {
    #pragma unroll
    for (int off = 16; off >= 1; off >>= 1)
        v += __shfl_xor_sync(0xffffffffu, v, off);
    return v;
}

// One-time prep: transpose W to o-contiguous dual-pairs, zero accumulators.
__global__ void prep_kernel(const float* __restrict__ w) {
    int idx = blockIdx.x * 256 + threadIdx.x;   // grid covers 32768
    if (idx < Ii * 4 * Oo) {
        int o = idx & 63, k = (idx >> 6) & 3, ic = idx >> 8;
        const float4 s = *(const float4*)(w + ((ic * Oo + o) * 16 + k * 4));
        ulonglong2 d;
        d.x = ((u64t)__float_as_uint(s.y) << 32) | __float_as_uint(s.x);
        d.y = ((u64t)__float_as_uint(s.w) << 32) | __float_as_uint(s.z);
        g_wT2[idx] = d;
    }
    float* s0 = &g_S0[0][0];
    float* s1 = &g_S1[0][0][0];
    float* s2 = &g_S2[0][0][0];
    if (idx < Bb * Oo) s0[idx] = 0.0f;
    if (idx < Bb * Oo * Pp) { s1[idx] = 0.0f; s2[idx] = 0.0f; }
}

// Shared layout (floats): mean(1280) inv(1280) ll(64) pose(2048) act(128)
//                         acc0(64) acc1(1088) acc2(1088)  = 7040 floats = 27.5KB
template<bool FIRST>
__global__ __launch_bounds__(128, 4)
void stats_kernel(const float* __restrict__ gpose,
                  const float* __restrict__ gact)
{
    __shared__ float sm[7040];
    float* sMean = sm;             // negated mean, stride WS
    float* sInv  = sm + 1280;      // 1/(2 var), stride WS
    float* sLL   = sm + 2560;
    float* sPose = sm + 2624;
    float* sAct  = sm + 4672;
    float* sAcc0 = sm + 4800;
    float* sAcc1 = sm + 4864;      // stride AS per o
    float* sAcc2 = sm + 5952;

    const int tid   = threadIdx.x;
    const int b     = blockIdx.y;
    const int chunk = blockIdx.x;

    // ---- stage pose + act ----
    const float4* gp4 = (const float4*)(gpose + ((size_t)(b * Nn + chunk * ROWS)) * 16);
    #pragma unroll
    for (int i = 0; i < 4; i++)
        ((float4*)sPose)[tid + 128 * i] = gp4[tid + 128 * i];
    sAct[tid] = gact[b * Nn + chunk * ROWS + tid];

    if (!FIRST) {
        for (int idx = tid; idx < Oo * Pp; idx += 128) {
            int o = idx >> 4, p = idx & 15;
            sMean[o * WS + p] = -g_mean[b][o][p];
            sInv[o * WS + p]  = g_inv2var[b][o][p];
        }
        if (tid < Oo) sLL[tid] = g_ll[b][tid];
    }
    for (int idx = tid; idx < 64 + 2 * 1088; idx += 128) sAcc0[idx] = 0.0f;
    __syncthreads();

    const int wid  = tid >> 5;
    const int lane = tid & 31;
    const int sp   = chunk * 4 + wid;              // global spatial [0,64)
    const float chv = ((sp >> 3) + 0.5f) * 0.125f;
    const float cwv = ((sp & 7) + 0.5f) * 0.125f;

    float ll0 = 0.0f, ll1 = 0.0f;
    if (!FIRST) { ll0 = sLL[lane]; ll1 = sLL[lane + 32]; }

    u64t A1[2][8], A2[2][8];
    float A0[2] = {0.0f, 0.0f};
    #pragma unroll
    for (int j = 0; j < 2; j++)
        #pragma unroll
        for (int r2 = 0; r2 < 8; r2++) { A1[j][r2] = 0ull; A2[j][r2] = 0ull; }

    for (int ic = 0; ic < Ii; ic++) {
        const int r = wid * 32 + ic;

        // pose row -> 16 floats (broadcast LDS128)
        float pr[16];
        {
            const float4* pp = (const float4*)&sPose[r * 16];
            #pragma unroll
            for (int q = 0; q < 4; q++) {
                float4 t = pp[q];
                pr[q*4+0] = t.x; pr[q*4+1] = t.y; pr[q*4+2] = t.z; pr[q*4+3] = t.w;
            }
        }
        const float a_n = sAct[r];

        // ---- votes for BOTH o-halves, loads paired per k for max MLP ----
        u64t va[8], vb[8];
        va[0] = pk2(chv, cwv);  vb[0] = va[0];
        #pragma unroll
        for (int r2 = 1; r2 < 8; r2++) { va[r2] = 0ull; vb[r2] = 0ull; }

        const ulonglong2* wb = g_wT2 + ic * 256;
        #pragma unroll
        for (int k = 0; k < 4; k++) {
            ulonglong2 wk0 = __ldg(wb + k * 64 + lane);        // o = lane
            ulonglong2 wk1 = __ldg(wb + k * 64 + lane + 32);   // o = lane+32
            #pragma unroll
            for (int a = 0; a < 4; a++) {
                u64t pa = pk2(pr[a*4+k], pr[a*4+k]);
                va[a*2+0] = fma2(pa, wk0.x, va[a*2+0]);
                va[a*2+1] = fma2(pa, wk0.y, va[a*2+1]);
                vb[a*2+0] = fma2(pa, wk1.x, vb[a*2+0]);
                vb[a*2+1] = fma2(pa, wk1.y, vb[a*2+1]);
            }
        }

        // ---- distances for both halves, interleaved chains ----
        float zz0 = 0.0f, zz1 = 0.0f;
        if (!FIRST) {
            u64t acca = 0ull, accb = 0ull;
            const ulonglong2* mra = (const ulonglong2*)&sMean[lane * WS];
            const ulonglong2* ira = (const ulonglong2*)&sInv[lane * WS];
            const ulonglong2* mrb = (const ulonglong2*)&sMean[(lane + 32) * WS];
            const ulonglong2* irb = (const ulonglong2*)&sInv[(lane + 32) * WS];
            #pragma unroll
            for (int q = 0; q < 4; q++) {
                ulonglong2 ma  = mra[q], iva = ira[q];
                ulonglong2 mb  = mrb[q], ivb = irb[q];
                u64t d0a = add2(va[q*2+0], ma.x);
                u64t d0b = add2(vb[q*2+0], mb.x);
                acca = fma2(mul2(d0a, d0a), iva.x, acca);
                accb = fma2(mul2(d0b, d0b), ivb.x, accb);
                u64t d1a = add2(va[q*2+1], ma.y);
                u64t d1b = add2(vb[q*2+1], mb.y);
                acca = fma2(mul2(d1a, d1a), iva.y, acca);
                accb = fma2(mul2(d1b, d1b), ivb.y, accb);
            }
            float al, ah, bl, bh;
            up2(acca, al, ah);
            up2(accb, bl, bh);
            zz0 = ll0 - (al + ah);
            zz1 = ll1 - (bl + bh);
        }

        float rrp0, rrp1;
        if (!FIRST) {
            float m = warp_max(fmaxf(zz0, zz1));
            float e0 = __expf(zz0 - m);
            float e1 = __expf(zz1 - m);
            float s = warp_add(e0 + e1);
            float scale = __fdividef(a_n, s);
            rrp0 = e0 * scale;
            rrp1 = e1 * scale;
        } else {
            rrp0 = rrp1 = a_n * (1.0f / 64.0f);
        }

        A0[0] += rrp0;
        A0[1] += rrp1;
        u64t rp0 = pk2(rrp0, rrp0);
        u64t rp1 = pk2(rrp1, rrp1);
        #pragma unroll
        for (int r2 = 0; r2 < 8; r2++) {
            u64t ta = mul2(rp0, va[r2]);
            u64t tb = mul2(rp1, vb[r2]);
            A1[0][r2] = add2(A1[0][r2], ta);
            A1[1][r2] = add2(A1[1][r2], tb);
            A2[0][r2] = fma2(ta, va[r2], A2[0][r2]);
            A2[1][r2] = fma2(tb, vb[r2], A2[1][r2]);
        }
    }

    // ---- cross-warp reduction (conflict-free smem atomics, stride AS) ----
    #pragma unroll
    for (int j2 = 0; j2 < 2; j2++) {
        const int o = lane + 32 * j2;
        atomicAdd(&sAcc0[o], A0[j2]);
        #pragma unroll
        for (int r2 = 0; r2 < 8; r2++) {
            float l1, h1, l2h, h2h;
            up2(A1[j2][r2], l1, h1);
            up2(A2[j2][r2], l2h, h2h);
            atomicAdd(&sAcc1[o * AS + 2*r2],     l1);
            atomicAdd(&sAcc1[o * AS + 2*r2 + 1], h1);
            atomicAdd(&sAcc2[o * AS + 2*r2],     l2h);
            atomicAdd(&sAcc2[o * AS + 2*r2 + 1], h2h);
        }
    }
    __syncthreads();

    // ---- flush partials to global accumulators ----
    float* gs0 = &g_S0[b][0];
    float* gs1 = &g_S1[b][0][0];
    float* gs2 = &g_S2[b][0][0];
    for (int idx = tid; idx < Oo; idx += 128) atomicAdd(&gs0[idx], sAcc0[idx]);
    for (int idx = tid; idx < Oo * Pp; idx += 128) {
        int o = idx >> 4, p = idx & 15;
        atomicAdd(&gs1[idx], sAcc1[o * AS + p]);
        atomicAdd(&gs2[idx], sAcc2[o * AS + p]);
    }
}

__global__ __launch_bounds__(64)
void finalize_kernel(int it,
                     const float* __restrict__ beta_v,
                     const float* __restrict__ beta_a,
                     float* __restrict__ out)
{
    __shared__ float sCost[Oo];
    const int b = blockIdx.x;
    const int o = threadIdx.x;

    const float rps = g_S0[b][o];
    const float inv_rps = 1.0f / rps;
    float mean[16], inv2v[16];
    float lsum = 0.0f;
    #pragma unroll
    for (int p = 0; p < 16; p++) {
        float m = g_S1[b][o][p] * inv_rps;
        float var = g_S2[b][o][p] * inv_rps - m * m;
        var = fmaxf(var, 0.0f);
        float sd = sqrtf(var);
        mean[p] = m;
        inv2v[p] = 0.5f / var;
        lsum += __logf(sd + EPSF);
    }
    const float cost = (16.0f * beta_v[o] + lsum) * rps;
    sCost[o] = cost;
    __syncthreads();

    float cm = 0.0f;
    for (int q = 0; q < Oo; q++) cm += sCost[q];
    cm *= (1.0f / 64.0f);
    float cv = 0.0f;
    for (int q = 0; q < Oo; q++) { float d = sCost[q] - cm; cv += d * d; }
    const float cstd = sqrtf(cv * (1.0f / 64.0f));

    const float inv_temp = 1.0f + (float)it;
    const float x = inv_temp * (beta_a[o] + (cm - cost) / (cstd + EPSF));
    const float oact = 1.0f / (1.0f + __expf(-x));

    if (it < 2) {
        g_ll[b][o] = __logf(oact + EPSF) - lsum;
        #pragma unroll
        for (int p = 0; p < 16; p++) {
            g_mean[b][o][p] = mean[p];
            g_inv2var[b][o][p] = inv2v[p];
        }
        g_S0[b][o] = 0.0f;
        #pragma unroll
        for (int p = 0; p < 16; p++) { g_S1[b][o][p] = 0.0f; g_S2[b][o][p] = 0.0f; }
    } else {
        #pragma unroll
        for (int p = 0; p < 16; p++) out[(b * Oo + o) * 16 + p] = mean[p];
        out[Bb * Oo * Pp + b * Oo + o] = oact;
    }
}

extern "C" void kernel_launch(void* const* d_in, const int* in_sizes, int n_in,
                              void* d_out, int out_size)
{
    const float* pose = (const float*)d_in[0];
    const float* act  = (const float*)d_in[1];
    const float* w    = (const float*)d_in[2];
    const float* bv   = (const float*)d_in[3];
    const float* ba   = (const float*)d_in[4];
    float* out = (float*)d_out;

    prep_kernel<<<128, 256>>>(w);
    stats_kernel<true><<<dim3(CHUNKS, Bb), 128>>>(pose, act);
    finalize_kernel<<<Bb, 64>>>(0, bv, ba, out);
    stats_kernel<false><<<dim3(CHUNKS, Bb), 128>>>(pose, act);
    finalize_kernel<<<Bb, 64>>>(1, bv, ba, out);
    stats_kernel<false><<<dim3(CHUNKS, Bb), 128>>>(pose, act);
    finalize_kernel<<<Bb, 64>>>(2, bv, ba, out);
}